// round 12
// baseline (speedup 1.0000x reference)
#include <cuda_runtime.h>
#include <cuda_fp16.h>

#define NN 50000
#define EE 800000
#define CC 64
#define BN_EPS 1e-5f

// ---------------- packed f32x2 helpers (Blackwell sm_103a) -------------------
#define PACK_DUP2(out, f) \
    asm("mov.b64 %0, {%1, %1};" : "=l"(out) : "r"(__float_as_uint(f)))
#define PACK2(out, f0, f1) \
    asm("mov.b64 %0, {%1, %2};" : "=l"(out) : "r"(__float_as_uint(f0)), "r"(__float_as_uint(f1)))
#define FMA2(d, a, b) \
    asm("fma.rn.f32x2 %0, %1, %2, %0;" : "+l"(d) : "l"(a), "l"(b))
#define UNPACK2(lo, hi, v) \
    asm("mov.b64 {%0, %1}, %2;" : "=r"(lo), "=r"(hi) : "l"(v))

// ---------------- scratch (static device arrays; no allocation) -------------
__device__ float2   g_cs[NN];        // (sum s, sum s^2) per src node
__device__ float    g_S1[CC];
__device__ float    g_S2[CC];
__device__ float    g_hsum[CC];
__device__ float    g_hsq[CC];
__device__ __half2  g_Yh[NN * 32];   // X @ pool_W, fp16x2 (k4 gather only)
__device__ float    g_aggf[NN * CC]; // scatter-max result (>= 0)

// ---------------- K0: zero small per-replay state -----------------------------
__global__ void k0_zero() {
    int i = blockIdx.x * blockDim.x + threadIdx.x;
    if (i < NN) g_cs[i] = make_float2(0.f, 0.f);
    if (i < CC) { g_S1[i] = 0.f; g_S2[i] = 0.f; g_hsum[i] = 0.f; g_hsq[i] = 0.f; }
}

// ---------------- K1z: zero scatter-max target (side stream, joins before k4) --
__global__ void k1z_zero_agg() {
    int i = blockIdx.x * blockDim.x + threadIdx.x;
    int stride = gridDim.x * blockDim.x;
    float4 z = make_float4(0.f, 0.f, 0.f, 0.f);
    float4* a4 = reinterpret_cast<float4*>(g_aggf);
    for (int idx = i; idx < NN * CC / 4; idx += stride) a4[idx] = z;
}

// ---------------- K1: per-src sums of s, s^2 -----------------------------------
__global__ void k1_edge_stats(const int* __restrict__ ei,
                              const float* __restrict__ ew,
                              const float* __restrict__ coefp) {
    int i = blockIdx.x * blockDim.x + threadIdx.x;
    if (i >= EE) return;
    float coef = __ldg(coefp);
    int src = ei[i];
    float s = fmaf(coef, ew[i], 1.0f);
    atomicAdd(&g_cs[src].x, s);
    atomicAdd(&g_cs[src].y, s * s);
}

// ---------------- K2: Y = X @ pool_W (f32x2) + fused BN-stats, fp16 Y out -----
// 128 threads (4 warps). Warp w: column-half (w&1), row-group (w>>1).
// Thread handles 2 rows x 32 cols. Stats partials stream straight to smem.
__global__ void __launch_bounds__(128) k2_xw(const float* __restrict__ x,
                                             const float* __restrict__ W) {
    __shared__ float Ws[8320];   // 4096 weights; 4x2080 conflict-free reduction
    {
        const float4* W4 = reinterpret_cast<const float4*>(W);
        float4* Ws4 = reinterpret_cast<float4*>(Ws);
        for (int i = threadIdx.x; i < CC * CC / 4; i += 128) Ws4[i] = W4[i];
    }
    __syncthreads();
    int wid  = threadIdx.x >> 5;
    int half = wid & 1;
    int grp  = wid >> 1;
    int lane = threadIdx.x & 31;
    int rbase = blockIdx.x * 128 + grp * 64 + lane;
    int r[2]; bool ok[2];
#pragma unroll
    for (int j = 0; j < 2; j++) { r[j] = rbase + 32 * j; ok[j] = r[j] < NN; }

    unsigned long long acc[2][16];
#pragma unroll
    for (int j = 0; j < 2; j++)
#pragma unroll
        for (int p = 0; p < 16; p++) acc[j][p] = 0ull;

    const float4 z4 = make_float4(0.f, 0.f, 0.f, 0.f);
#pragma unroll 4
    for (int k4 = 0; k4 < 16; k4++) {
        float4 xv[2];
#pragma unroll
        for (int j = 0; j < 2; j++)
            xv[j] = ok[j] ? *reinterpret_cast<const float4*>(
                                x + (size_t)r[j] * CC + k4 * 4)
                          : z4;
        float xk[2][4];
#pragma unroll
        for (int j = 0; j < 2; j++) {
            xk[j][0] = xv[j].x; xk[j][1] = xv[j].y;
            xk[j][2] = xv[j].z; xk[j][3] = xv[j].w;
        }
#pragma unroll
        for (int kk = 0; kk < 4; kk++) {
            unsigned long long a[2];
#pragma unroll
            for (int j = 0; j < 2; j++) PACK_DUP2(a[j], xk[j][kk]);
            const ulonglong2* wr = reinterpret_cast<const ulonglong2*>(
                &Ws[(k4 * 4 + kk) * CC + half * 32]);
#pragma unroll
            for (int p = 0; p < 8; p++) {
                ulonglong2 w = wr[p];
#pragma unroll
                for (int j = 0; j < 2; j++) {
                    FMA2(acc[j][2 * p],     a[j], w.x);
                    FMA2(acc[j][2 * p + 1], a[j], w.y);
                }
            }
        }
    }

    // epilogue: weights dead after this barrier — stream partials into smem
    float2 cs[2];
#pragma unroll
    for (int j = 0; j < 2; j++)
        cs[j] = ok[j] ? g_cs[r[j]] : make_float2(0.f, 0.f);
    __syncthreads();
    float* red = Ws + wid * 2080;
#pragma unroll
    for (int j = 0; j < 2; j++) {
        float yv[32];
#pragma unroll
        for (int p = 0; p < 16; p++) {
            unsigned u0, u1;
            UNPACK2(u0, u1, acc[j][p]);
            yv[2 * p]     = __uint_as_float(u0);
            yv[2 * p + 1] = __uint_as_float(u1);
        }
        if (ok[j]) {
            __half2 hh[16];
#pragma unroll
            for (int c2 = 0; c2 < 16; c2++)
                hh[c2] = __floats2half2_rn(yv[2 * c2], yv[2 * c2 + 1]);
            uint4* dst = reinterpret_cast<uint4*>(g_Yh + (size_t)r[j] * 32 + half * 16);
            const uint4* srcv = reinterpret_cast<const uint4*>(hh);
#pragma unroll
            for (int q = 0; q < 4; q++) dst[q] = srcv[q];
        }
        if (j == 0) {
#pragma unroll
            for (int c = 0; c < 32; c++) {
                red[lane * 65 + c]      = cs[0].x * yv[c];
                red[lane * 65 + 32 + c] = cs[0].y * yv[c] * yv[c];
            }
        } else {
#pragma unroll
            for (int c = 0; c < 32; c++) {
                red[lane * 65 + c]      += cs[1].x * yv[c];
                red[lane * 65 + 32 + c] += cs[1].y * yv[c] * yv[c];
            }
        }
    }
    __syncwarp();
    float a = 0.f, b = 0.f;
#pragma unroll
    for (int k = 0; k < 32; k++) {
        a += red[k * 65 + lane];
        b += red[k * 65 + 32 + lane];
    }
    atomicAdd(&g_S1[half * 32 + lane], a);
    atomicAdd(&g_S2[half * 32 + lane], b);
}

// ---------------- K4: filtered scatter-max (round-6 exact shape) ---------------
__global__ void __launch_bounds__(256) k4_scatter(const int* __restrict__ ei,
                                                  const float* __restrict__ ew,
                                                  const float* __restrict__ coefp,
                                                  const float* __restrict__ pb,
                                                  const float* __restrict__ gamma,
                                                  const float* __restrict__ beta) {
    __shared__ float s_al[CC], s_de[CC];
    if (threadIdx.x < CC) {
        int c = threadIdx.x;
        float invE = 1.0f / (float)EE;
        float bb = pb[c];
        float mean = g_S1[c] * invE + bb;
        float msq = (g_S2[c] + 2.f * bb * g_S1[c]) * invE + bb * bb;
        float var = msq - mean * mean;
        float alpha = gamma[c] * rsqrtf(var + BN_EPS);
        s_al[c] = alpha;
        s_de[c] = beta[c] + alpha * (bb - mean);
    }
    __syncthreads();
    float coef = __ldg(coefp);
    int lane = threadIdx.x & 31;
    int warp = (blockIdx.x * blockDim.x + threadIdx.x) >> 5;
    int nwarps = (gridDim.x * blockDim.x) >> 5;
    float al0 = s_al[2 * lane], al1 = s_al[2 * lane + 1];
    float de0 = s_de[2 * lane], de1 = s_de[2 * lane + 1];
    for (int base = warp * 32; base < EE; base += nwarps * 32) {
        int e = base + lane;
        int src = ei[e];
        int dst = ei[EE + e];
        float s = fmaf(coef, ew[e], 1.0f);
#pragma unroll 8
        for (int i = 0; i < 32; i++) {
            int   sI = __shfl_sync(0xffffffffu, src, i);
            int   dI = __shfl_sync(0xffffffffu, dst, i);
            float sS = __shfl_sync(0xffffffffu, s, i);
            __half2 yh = __ldg(g_Yh + (size_t)sI * 32 + lane);
            float2 yv = __half22float2(yh);
            float v0 = fmaf(al0 * sS, yv.x, de0);
            float v1 = fmaf(al1 * sS, yv.y, de1);
            float* arow = g_aggf + (size_t)dI * CC + 2 * lane;
            float2 cur = *reinterpret_cast<const float2*>(arow);
            unsigned* au = reinterpret_cast<unsigned*>(arow);
            if (v0 > cur.x) atomicMax(au,     __float_as_uint(v0));
            if (v1 > cur.y) atomicMax(au + 1, __float_as_uint(v1));
        }
    }
}

// ---------------- K5: h = [x, agg] @ final_W + b (f32x2) + fused h-stats -------
// 128 threads (4 warps), 2 rows/thread; stats partials stream to smem.
__global__ void __launch_bounds__(128) k5_final(const float* __restrict__ x,
                                                const float* __restrict__ Wf,
                                                const float* __restrict__ fb,
                                                float* __restrict__ hout) {
    __shared__ float Ws[8320];   // 8192 weights; reused as 4x2080 reduction
    {
        const float4* W4 = reinterpret_cast<const float4*>(Wf);
        float4* Ws4 = reinterpret_cast<float4*>(Ws);
        for (int i = threadIdx.x; i < 2 * CC * CC / 4; i += 128) Ws4[i] = W4[i];
    }
    __syncthreads();
    int wid  = threadIdx.x >> 5;
    int half = wid & 1;
    int grp  = wid >> 1;
    int lane = threadIdx.x & 31;
    int rbase = blockIdx.x * 128 + grp * 64 + lane;
    int r[2]; bool ok[2];
#pragma unroll
    for (int j = 0; j < 2; j++) { r[j] = rbase + 32 * j; ok[j] = r[j] < NN; }

    unsigned long long acc[2][16];
    {
        const float* fbh = fb + half * 32;
        unsigned long long binit[16];
#pragma unroll
        for (int p = 0; p < 16; p++) PACK2(binit[p], fbh[2 * p], fbh[2 * p + 1]);
#pragma unroll
        for (int j = 0; j < 2; j++)
#pragma unroll
            for (int p = 0; p < 16; p++) acc[j][p] = binit[p];
    }

    const float4 z4 = make_float4(0.f, 0.f, 0.f, 0.f);
#pragma unroll
    for (int ph = 0; ph < 2; ph++) {
        const float* src = (ph == 0) ? x : g_aggf;
        const float* Wb  = Ws + ph * CC * CC;
#pragma unroll 4
        for (int k4 = 0; k4 < 16; k4++) {
            float4 xv[2];
#pragma unroll
            for (int j = 0; j < 2; j++)
                xv[j] = ok[j] ? *reinterpret_cast<const float4*>(
                                    src + (size_t)r[j] * CC + k4 * 4)
                              : z4;
            float xk[2][4];
#pragma unroll
            for (int j = 0; j < 2; j++) {
                xk[j][0] = xv[j].x; xk[j][1] = xv[j].y;
                xk[j][2] = xv[j].z; xk[j][3] = xv[j].w;
            }
#pragma unroll
            for (int kk = 0; kk < 4; kk++) {
                unsigned long long a[2];
#pragma unroll
                for (int j = 0; j < 2; j++) PACK_DUP2(a[j], xk[j][kk]);
                const ulonglong2* wr = reinterpret_cast<const ulonglong2*>(
                    &Wb[(k4 * 4 + kk) * CC + half * 32]);
#pragma unroll
                for (int p = 0; p < 8; p++) {
                    ulonglong2 w = wr[p];
#pragma unroll
                    for (int j = 0; j < 2; j++) {
                        FMA2(acc[j][2 * p],     a[j], w.x);
                        FMA2(acc[j][2 * p + 1], a[j], w.y);
                    }
                }
            }
        }
    }

    // epilogue: weights dead after this barrier — stream partials into smem
    __syncthreads();
    float* red = Ws + wid * 2080;
#pragma unroll
    for (int j = 0; j < 2; j++) {
        float hv[32];
#pragma unroll
        for (int p = 0; p < 16; p++) {
            unsigned u0, u1;
            UNPACK2(u0, u1, acc[j][p]);
            hv[2 * p]     = __uint_as_float(u0);
            hv[2 * p + 1] = __uint_as_float(u1);
        }
        float m = ok[j] ? 1.f : 0.f;
        if (ok[j]) {
            float* dst = hout + (size_t)r[j] * CC + half * 32;
#pragma unroll
            for (int q = 0; q < 8; q++) {
                float4 v;
                v.x = hv[4 * q]; v.y = hv[4 * q + 1];
                v.z = hv[4 * q + 2]; v.w = hv[4 * q + 3];
                *reinterpret_cast<float4*>(dst + q * 4) = v;
            }
        }
        if (j == 0) {
#pragma unroll
            for (int c = 0; c < 32; c++) {
                red[lane * 65 + c]      = m * hv[c];
                red[lane * 65 + 32 + c] = m * hv[c] * hv[c];
            }
        } else {
#pragma unroll
            for (int c = 0; c < 32; c++) {
                red[lane * 65 + c]      += m * hv[c];
                red[lane * 65 + 32 + c] += m * hv[c] * hv[c];
            }
        }
    }
    __syncwarp();
    float a = 0.f, b = 0.f;
#pragma unroll
    for (int k = 0; k < 32; k++) {
        a += red[k * 65 + lane];
        b += red[k * 65 + 32 + lane];
    }
    atomicAdd(&g_hsum[half * 32 + lane], a);
    atomicAdd(&g_hsq[half * 32 + lane], b);
}

// ---------------- K7: out = relu(a2*out + b2), in place (BN coeffs fused) ------
__global__ void __launch_bounds__(256) k7_epilogue(float* __restrict__ out,
                                                   const float* __restrict__ gamma,
                                                   const float* __restrict__ beta) {
    __shared__ float s_a[CC], s_b[CC];
    if (threadIdx.x < CC) {
        int c = threadIdx.x;
        float invN = 1.0f / (float)NN;
        float mean = g_hsum[c] * invN;
        float var = g_hsq[c] * invN - mean * mean;
        float a = gamma[c] * rsqrtf(var + BN_EPS);
        s_a[c] = a;
        s_b[c] = beta[c] - a * mean;
    }
    __syncthreads();
    int i = blockIdx.x * blockDim.x + threadIdx.x;
    int stride = gridDim.x * blockDim.x;
    float4* ov = reinterpret_cast<float4*>(out);
    for (int q = i; q < NN * 16; q += stride) {
        int c4 = (q & 15) * 4;
        float4 h = ov[q];
        float4 r;
        r.x = fmaxf(0.f, fmaf(s_a[c4 + 0], h.x, s_b[c4 + 0]));
        r.y = fmaxf(0.f, fmaf(s_a[c4 + 1], h.y, s_b[c4 + 1]));
        r.z = fmaxf(0.f, fmaf(s_a[c4 + 2], h.z, s_b[c4 + 2]));
        r.w = fmaxf(0.f, fmaf(s_a[c4 + 3], h.w, s_b[c4 + 3]));
        ov[q] = r;
    }
}

// ---------------- launch: fork agg-zero onto a side stream ---------------------
extern "C" void kernel_launch(void* const* d_in, const int* in_sizes, int n_in,
                              void* d_out, int out_size) {
    const float* x     = (const float*)d_in[0];
    const int*   ei    = (const int*)d_in[1];
    const float* ew    = (const float*)d_in[2];
    const float* pW    = (const float*)d_in[3];
    const float* pb    = (const float*)d_in[4];
    const float* pg    = (const float*)d_in[5];
    const float* pbeta = (const float*)d_in[6];
    const float* fW    = (const float*)d_in[7];
    const float* fb    = (const float*)d_in[8];
    const float* fg    = (const float*)d_in[9];
    const float* fbeta = (const float*)d_in[10];
    const float* coef  = (const float*)d_in[11];
    float* out = (float*)d_out;

    const int rowBlocks = (NN + 127) / 128;   // 391

    cudaStream_t s2;
    cudaEvent_t evFork, evJoin;
    cudaStreamCreateWithFlags(&s2, cudaStreamNonBlocking);
    cudaEventCreateWithFlags(&evFork, cudaEventDisableTiming);
    cudaEventCreateWithFlags(&evJoin, cudaEventDisableTiming);

    // fork: agg zero runs concurrently with k0/k1/k2
    cudaEventRecord(evFork, 0);
    cudaStreamWaitEvent(s2, evFork, 0);
    k1z_zero_agg<<<1184, 256, 0, s2>>>();
    cudaEventRecord(evJoin, s2);

    k0_zero<<<(NN + 255) / 256, 256>>>();
    k1_edge_stats<<<(EE + 255) / 256, 256>>>(ei, ew, coef);
    k2_xw<<<rowBlocks, 128>>>(x, pW);

    // join: k4 needs the zeroed agg buffer
    cudaStreamWaitEvent(0, evJoin, 0);
    k4_scatter<<<1184, 256>>>(ei, ew, coef, pb, pg, pbeta);
    k5_final<<<rowBlocks, 128>>>(x, fW, fb, out);
    k7_epilogue<<<1024, 256>>>(out, fg, fbeta);
}

// round 13
// speedup vs baseline: 1.1318x; 1.1318x over previous
#include <cuda_runtime.h>
#include <cuda_fp16.h>

#define NN 50000
#define EE 800000
#define CC 64
#define BN_EPS 1e-5f

// ---------------- packed f32x2 helpers (Blackwell sm_103a) -------------------
#define PACK_DUP2(out, f) \
    asm("mov.b64 %0, {%1, %1};" : "=l"(out) : "r"(__float_as_uint(f)))
#define PACK2(out, f0, f1) \
    asm("mov.b64 %0, {%1, %2};" : "=l"(out) : "r"(__float_as_uint(f0)), "r"(__float_as_uint(f1)))
#define FMA2(d, a, b) \
    asm("fma.rn.f32x2 %0, %1, %2, %0;" : "+l"(d) : "l"(a), "l"(b))
#define UNPACK2(lo, hi, v) \
    asm("mov.b64 {%0, %1}, %2;" : "=r"(lo), "=r"(hi) : "l"(v))

#define MMA16816(c0, c1, c2, c3, a0, a1, a2, a3, b0, b1) \
    asm volatile("mma.sync.aligned.m16n8k16.row.col.f32.f16.f16.f32 " \
        "{%0,%1,%2,%3}, {%4,%5,%6,%7}, {%8,%9}, {%0,%1,%2,%3};" \
        : "+f"(c0), "+f"(c1), "+f"(c2), "+f"(c3) \
        : "r"(a0), "r"(a1), "r"(a2), "r"(a3), "r"(b0), "r"(b1))

// ---------------- scratch (static device arrays; no allocation) -------------
__device__ float2   g_cs[NN];        // (sum s, sum s^2) per src node
__device__ float    g_S1[CC];
__device__ float    g_S2[CC];
__device__ float    g_hsum[CC];
__device__ float    g_hsq[CC];
__device__ __half2  g_Yh[NN * 32];   // X @ pool_W, fp16x2 (k4 gather only)
__device__ float    g_aggf[NN * CC]; // scatter-max result (>= 0)

// ---------------- K0: zero small per-replay state -----------------------------
__global__ void k0_zero() {
    int i = blockIdx.x * blockDim.x + threadIdx.x;
    if (i < NN) g_cs[i] = make_float2(0.f, 0.f);
    if (i < CC) { g_S1[i] = 0.f; g_S2[i] = 0.f; g_hsum[i] = 0.f; g_hsq[i] = 0.f; }
}

// ---------------- K1: per-src sums of s, s^2 + zero agg ------------------------
__global__ void k1_edge_stats(const int* __restrict__ ei,
                              const float* __restrict__ ew,
                              const float* __restrict__ coefp) {
    int i = blockIdx.x * blockDim.x + threadIdx.x;
    int stride = gridDim.x * blockDim.x;
    // zero scatter-max target (safe: k1 atomics touch only g_cs; k4 runs later)
    float4 z = make_float4(0.f, 0.f, 0.f, 0.f);
    float4* a4 = reinterpret_cast<float4*>(g_aggf);
    for (int idx = i; idx < NN * CC / 4; idx += stride) a4[idx] = z;
    if (i >= EE) return;
    float coef = __ldg(coefp);
    int src = ei[i];
    float s = fmaf(coef, ew[i], 1.0f);
    atomicAdd(&g_cs[src].x, s);
    atomicAdd(&g_cs[src].y, s * s);
}

// ---------------- K2: Y = X @ pool_W via HMMA (fp16 in, fp32 accum) -----------
// 256 threads (8 warps). Block tile = 128 rows. Warp w: rows [w*16, w*16+16).
// x staged coalesced -> fp16 smem (pitch 72 halves, conflict-free frag loads);
// W transposed -> fp16 smem Wt[c][k]. Stats from fp32 accums; Y stored half2.
__global__ void __launch_bounds__(256) k2_xw(const float* __restrict__ x,
                                             const float* __restrict__ W) {
    __shared__ __align__(16) __half xs[128 * 72];   // 18432 B
    __shared__ __align__(16) __half ws[64 * 72];    //  9216 B, Wt[c][k]
    __shared__ float s1buf[8][64];
    __shared__ float s2buf[8][64];

    int tid = threadIdx.x;
    int rowbase = blockIdx.x * 128;

    // stage W (transpose, fp16)
    for (int i = tid; i < CC * CC; i += 256) {
        int k = i >> 6, c = i & 63;
        ws[c * 72 + k] = __float2half_rn(W[i]);
    }
    // stage x tile (coalesced, fp16)
    const float4 z4 = make_float4(0.f, 0.f, 0.f, 0.f);
    for (int i = tid; i < 128 * 16; i += 256) {
        int r = i >> 4, c4 = i & 15;
        int row = rowbase + r;
        float4 v = (row < NN) ? *reinterpret_cast<const float4*>(x + (size_t)row * CC + c4 * 4)
                              : z4;
        __half2* d = reinterpret_cast<__half2*>(&xs[r * 72 + c4 * 4]);
        d[0] = __floats2half2_rn(v.x, v.y);
        d[1] = __floats2half2_rn(v.z, v.w);
    }
    __syncthreads();

    int wid  = tid >> 5;
    int lane = tid & 31;
    int g = lane >> 2;       // groupID 0..7
    int q = lane & 3;        // quad 0..3
    int rloc = wid * 16;

    // A fragments: 4 k-steps x 4 u32
    unsigned afr[4][4];
#pragma unroll
    for (int ks = 0; ks < 4; ks++) {
        int k0 = ks * 16 + 2 * q;
        afr[ks][0] = *reinterpret_cast<const unsigned*>(&xs[(rloc + g) * 72 + k0]);
        afr[ks][1] = *reinterpret_cast<const unsigned*>(&xs[(rloc + g + 8) * 72 + k0]);
        afr[ks][2] = *reinterpret_cast<const unsigned*>(&xs[(rloc + g) * 72 + k0 + 8]);
        afr[ks][3] = *reinterpret_cast<const unsigned*>(&xs[(rloc + g + 8) * 72 + k0 + 8]);
    }

    float c[8][4];
#pragma unroll
    for (int nt = 0; nt < 8; nt++)
#pragma unroll
        for (int v = 0; v < 4; v++) c[nt][v] = 0.f;

#pragma unroll
    for (int nt = 0; nt < 8; nt++) {
        int n = nt * 8 + g;
#pragma unroll
        for (int ks = 0; ks < 4; ks++) {
            int kk = ks * 16 + 2 * q;
            unsigned b0 = *reinterpret_cast<const unsigned*>(&ws[n * 72 + kk]);
            unsigned b1 = *reinterpret_cast<const unsigned*>(&ws[n * 72 + kk + 8]);
            MMA16816(c[nt][0], c[nt][1], c[nt][2], c[nt][3],
                     afr[ks][0], afr[ks][1], afr[ks][2], afr[ks][3], b0, b1);
        }
    }

    // epilogue: Y (fp16) store + BN-stat partials
    int row0 = rowbase + rloc + g;
    int row1 = row0 + 8;
    bool ok0 = row0 < NN, ok1 = row1 < NN;
    float2 cs0 = ok0 ? g_cs[row0] : make_float2(0.f, 0.f);
    float2 cs1 = ok1 ? g_cs[row1] : make_float2(0.f, 0.f);

#pragma unroll
    for (int nt = 0; nt < 8; nt++) {
        // store col pair (nt*8 + 2q, +1) for rows row0/row1
        if (ok0) g_Yh[(size_t)row0 * 32 + nt * 4 + q] = __floats2half2_rn(c[nt][0], c[nt][1]);
        if (ok1) g_Yh[(size_t)row1 * 32 + nt * 4 + q] = __floats2half2_rn(c[nt][2], c[nt][3]);
        // per-column partials (2 cols per lane)
        float s1a = cs0.x * c[nt][0] + cs1.x * c[nt][2];
        float s1b = cs0.x * c[nt][1] + cs1.x * c[nt][3];
        float s2a = cs0.y * c[nt][0] * c[nt][0] + cs1.y * c[nt][2] * c[nt][2];
        float s2b = cs0.y * c[nt][1] * c[nt][1] + cs1.y * c[nt][3] * c[nt][3];
        // reduce over the 8 row-groups (lanes differing in bits 2..4)
#pragma unroll
        for (int off = 4; off < 32; off <<= 1) {
            s1a += __shfl_xor_sync(0xffffffffu, s1a, off);
            s1b += __shfl_xor_sync(0xffffffffu, s1b, off);
            s2a += __shfl_xor_sync(0xffffffffu, s2a, off);
            s2b += __shfl_xor_sync(0xffffffffu, s2b, off);
        }
        if (g == 0) {
            s1buf[wid][nt * 8 + 2 * q]     = s1a;
            s1buf[wid][nt * 8 + 2 * q + 1] = s1b;
            s2buf[wid][nt * 8 + 2 * q]     = s2a;
            s2buf[wid][nt * 8 + 2 * q + 1] = s2b;
        }
    }
    __syncthreads();
    if (tid < CC) {
        float a = 0.f, b = 0.f;
#pragma unroll
        for (int w = 0; w < 8; w++) { a += s1buf[w][tid]; b += s2buf[w][tid]; }
        atomicAdd(&g_S1[tid], a);
        atomicAdd(&g_S2[tid], b);
    }
}

// ---------------- K4: filtered scatter-max (round-6 exact shape) ---------------
__global__ void __launch_bounds__(256) k4_scatter(const int* __restrict__ ei,
                                                  const float* __restrict__ ew,
                                                  const float* __restrict__ coefp,
                                                  const float* __restrict__ pb,
                                                  const float* __restrict__ gamma,
                                                  const float* __restrict__ beta) {
    __shared__ float s_al[CC], s_de[CC];
    if (threadIdx.x < CC) {
        int c = threadIdx.x;
        float invE = 1.0f / (float)EE;
        float bb = pb[c];
        float mean = g_S1[c] * invE + bb;
        float msq = (g_S2[c] + 2.f * bb * g_S1[c]) * invE + bb * bb;
        float var = msq - mean * mean;
        float alpha = gamma[c] * rsqrtf(var + BN_EPS);
        s_al[c] = alpha;
        s_de[c] = beta[c] + alpha * (bb - mean);
    }
    __syncthreads();
    float coef = __ldg(coefp);
    int lane = threadIdx.x & 31;
    int warp = (blockIdx.x * blockDim.x + threadIdx.x) >> 5;
    int nwarps = (gridDim.x * blockDim.x) >> 5;
    float al0 = s_al[2 * lane], al1 = s_al[2 * lane + 1];
    float de0 = s_de[2 * lane], de1 = s_de[2 * lane + 1];
    for (int base = warp * 32; base < EE; base += nwarps * 32) {
        int e = base + lane;
        int src = ei[e];
        int dst = ei[EE + e];
        float s = fmaf(coef, ew[e], 1.0f);
#pragma unroll 8
        for (int i = 0; i < 32; i++) {
            int   sI = __shfl_sync(0xffffffffu, src, i);
            int   dI = __shfl_sync(0xffffffffu, dst, i);
            float sS = __shfl_sync(0xffffffffu, s, i);
            __half2 yh = __ldg(g_Yh + (size_t)sI * 32 + lane);
            float2 yv = __half22float2(yh);
            float v0 = fmaf(al0 * sS, yv.x, de0);
            float v1 = fmaf(al1 * sS, yv.y, de1);
            float* arow = g_aggf + (size_t)dI * CC + 2 * lane;
            float2 cur = *reinterpret_cast<const float2*>(arow);
            unsigned* au = reinterpret_cast<unsigned*>(arow);
            if (v0 > cur.x) atomicMax(au,     __float_as_uint(v0));
            if (v1 > cur.y) atomicMax(au + 1, __float_as_uint(v1));
        }
    }
}

// ---------------- K5: h = [x, agg] @ final_W + b (f32x2) + fused h-stats -------
// 128 threads (4 warps), 2 rows/thread, float4 weight prologue (round-9 exact).
__global__ void __launch_bounds__(128) k5_final(const float* __restrict__ x,
                                                const float* __restrict__ Wf,
                                                const float* __restrict__ fb,
                                                float* __restrict__ hout) {
    __shared__ float Ws[8320];   // 8192 weights; reused as 4x2080 reduction
    {
        const float4* W4 = reinterpret_cast<const float4*>(Wf);
        float4* Ws4 = reinterpret_cast<float4*>(Ws);
        for (int i = threadIdx.x; i < 2 * CC * CC / 4; i += 128) Ws4[i] = W4[i];
    }
    __syncthreads();
    int wid  = threadIdx.x >> 5;
    int half = wid & 1;
    int grp  = wid >> 1;
    int lane = threadIdx.x & 31;
    int rbase = blockIdx.x * 128 + grp * 64 + lane;
    int r[2]; bool ok[2];
#pragma unroll
    for (int j = 0; j < 2; j++) { r[j] = rbase + 32 * j; ok[j] = r[j] < NN; }

    unsigned long long acc[2][16];
    {
        const float* fbh = fb + half * 32;
        unsigned long long binit[16];
#pragma unroll
        for (int p = 0; p < 16; p++) PACK2(binit[p], fbh[2 * p], fbh[2 * p + 1]);
#pragma unroll
        for (int j = 0; j < 2; j++)
#pragma unroll
            for (int p = 0; p < 16; p++) acc[j][p] = binit[p];
    }

    const float4 z4 = make_float4(0.f, 0.f, 0.f, 0.f);
#pragma unroll
    for (int ph = 0; ph < 2; ph++) {
        const float* src = (ph == 0) ? x : g_aggf;
        const float* Wb  = Ws + ph * CC * CC;
#pragma unroll 4
        for (int k4 = 0; k4 < 16; k4++) {
            float4 xv[2];
#pragma unroll
            for (int j = 0; j < 2; j++)
                xv[j] = ok[j] ? *reinterpret_cast<const float4*>(
                                    src + (size_t)r[j] * CC + k4 * 4)
                              : z4;
            float xk[2][4];
#pragma unroll
            for (int j = 0; j < 2; j++) {
                xk[j][0] = xv[j].x; xk[j][1] = xv[j].y;
                xk[j][2] = xv[j].z; xk[j][3] = xv[j].w;
            }
#pragma unroll
            for (int kk = 0; kk < 4; kk++) {
                unsigned long long a[2];
#pragma unroll
                for (int j = 0; j < 2; j++) PACK_DUP2(a[j], xk[j][kk]);
                const ulonglong2* wr = reinterpret_cast<const ulonglong2*>(
                    &Wb[(k4 * 4 + kk) * CC + half * 32]);
#pragma unroll
                for (int p = 0; p < 8; p++) {
                    ulonglong2 w = wr[p];
#pragma unroll
                    for (int j = 0; j < 2; j++) {
                        FMA2(acc[j][2 * p],     a[j], w.x);
                        FMA2(acc[j][2 * p + 1], a[j], w.y);
                    }
                }
            }
        }
    }

    // epilogue: store h + accumulate per-channel sum / sumsq
    float p1[32], p2[32];
#pragma unroll
    for (int c = 0; c < 32; c++) { p1[c] = 0.f; p2[c] = 0.f; }
#pragma unroll
    for (int j = 0; j < 2; j++) {
        float hv[32];
#pragma unroll
        for (int p = 0; p < 16; p++) {
            unsigned u0, u1;
            UNPACK2(u0, u1, acc[j][p]);
            hv[2 * p]     = __uint_as_float(u0);
            hv[2 * p + 1] = __uint_as_float(u1);
        }
        if (ok[j]) {
            float* dst = hout + (size_t)r[j] * CC + half * 32;
#pragma unroll
            for (int q = 0; q < 8; q++) {
                float4 v;
                v.x = hv[4 * q]; v.y = hv[4 * q + 1];
                v.z = hv[4 * q + 2]; v.w = hv[4 * q + 3];
                *reinterpret_cast<float4*>(dst + q * 4) = v;
            }
#pragma unroll
            for (int c = 0; c < 32; c++) {
                p1[c] += hv[c];
                p2[c] += hv[c] * hv[c];
            }
        }
    }
    // conflict-free block reduction (stride 65)
    __syncthreads();
    float* red = Ws + wid * 2080;
#pragma unroll
    for (int c = 0; c < 32; c++) {
        red[lane * 65 + c]      = p1[c];
        red[lane * 65 + 32 + c] = p2[c];
    }
    __syncwarp();
    float a = 0.f, b = 0.f;
#pragma unroll
    for (int k = 0; k < 32; k++) {
        a += red[k * 65 + lane];
        b += red[k * 65 + 32 + lane];
    }
    atomicAdd(&g_hsum[half * 32 + lane], a);
    atomicAdd(&g_hsq[half * 32 + lane], b);
}

// ---------------- K7: out = relu(a2*out + b2), in place (BN coeffs fused) ------
__global__ void __launch_bounds__(256) k7_epilogue(float* __restrict__ out,
                                                   const float* __restrict__ gamma,
                                                   const float* __restrict__ beta) {
    __shared__ float s_a[CC], s_b[CC];
    if (threadIdx.x < CC) {
        int c = threadIdx.x;
        float invN = 1.0f / (float)NN;
        float mean = g_hsum[c] * invN;
        float var = g_hsq[c] * invN - mean * mean;
        float a = gamma[c] * rsqrtf(var + BN_EPS);
        s_a[c] = a;
        s_b[c] = beta[c] - a * mean;
    }
    __syncthreads();
    int i = blockIdx.x * blockDim.x + threadIdx.x;
    int stride = gridDim.x * blockDim.x;
    float4* ov = reinterpret_cast<float4*>(out);
    for (int q = i; q < NN * 16; q += stride) {
        int c4 = (q & 15) * 4;
        float4 h = ov[q];
        float4 r;
        r.x = fmaxf(0.f, fmaf(s_a[c4 + 0], h.x, s_b[c4 + 0]));
        r.y = fmaxf(0.f, fmaf(s_a[c4 + 1], h.y, s_b[c4 + 1]));
        r.z = fmaxf(0.f, fmaf(s_a[c4 + 2], h.z, s_b[c4 + 2]));
        r.w = fmaxf(0.f, fmaf(s_a[c4 + 3], h.w, s_b[c4 + 3]));
        ov[q] = r;
    }
}

// ---------------- launch ---------------------------------------------------------
extern "C" void kernel_launch(void* const* d_in, const int* in_sizes, int n_in,
                              void* d_out, int out_size) {
    const float* x     = (const float*)d_in[0];
    const int*   ei    = (const int*)d_in[1];
    const float* ew    = (const float*)d_in[2];
    const float* pW    = (const float*)d_in[3];
    const float* pb    = (const float*)d_in[4];
    const float* pg    = (const float*)d_in[5];
    const float* pbeta = (const float*)d_in[6];
    const float* fW    = (const float*)d_in[7];
    const float* fb    = (const float*)d_in[8];
    const float* fg    = (const float*)d_in[9];
    const float* fbeta = (const float*)d_in[10];
    const float* coef  = (const float*)d_in[11];
    float* out = (float*)d_out;

    const int rowBlocks = (NN + 127) / 128;   // 391
    k0_zero<<<(NN + 255) / 256, 256>>>();
    k1_edge_stats<<<(EE + 255) / 256, 256>>>(ei, ew, coef);
    k2_xw<<<rowBlocks, 256>>>(x, pW);
    k4_scatter<<<1184, 256>>>(ei, ew, coef, pb, pg, pbeta);
    k5_final<<<rowBlocks, 128>>>(x, fW, fb, out);
    k7_epilogue<<<1024, 256>>>(out, fg, fbeta);
}

// round 14
// speedup vs baseline: 1.4088x; 1.2447x over previous
#include <cuda_runtime.h>
#include <cuda_fp16.h>

#define NN 50000
#define EE 800000
#define CC 64
#define BN_EPS 1e-5f

#define MMA16816(c0, c1, c2, c3, a0, a1, a2, a3, b0, b1) \
    asm volatile("mma.sync.aligned.m16n8k16.row.col.f32.f16.f16.f32 " \
        "{%0,%1,%2,%3}, {%4,%5,%6,%7}, {%8,%9}, {%0,%1,%2,%3};" \
        : "+f"(c0), "+f"(c1), "+f"(c2), "+f"(c3) \
        : "r"(a0), "r"(a1), "r"(a2), "r"(a3), "r"(b0), "r"(b1))

// ---------------- scratch (static device arrays; no allocation) -------------
__device__ float2   g_cs[NN];        // (sum s, sum s^2) per src node
__device__ float    g_S1[CC];
__device__ float    g_S2[CC];
__device__ float    g_hsum[CC];
__device__ float    g_hsq[CC];
__device__ __half2  g_Yh[NN * 32];   // X @ pool_W, fp16x2 (k4 gather only)
__device__ float    g_aggf[NN * CC]; // scatter-max result (>= 0)

// ---------------- K0: zero small per-replay state -----------------------------
__global__ void k0_zero() {
    int i = blockIdx.x * blockDim.x + threadIdx.x;
    if (i < NN) g_cs[i] = make_float2(0.f, 0.f);
    if (i < CC) { g_S1[i] = 0.f; g_S2[i] = 0.f; g_hsum[i] = 0.f; g_hsq[i] = 0.f; }
}

// ---------------- K1: per-src sums of s, s^2 + zero agg ------------------------
__global__ void k1_edge_stats(const int* __restrict__ ei,
                              const float* __restrict__ ew,
                              const float* __restrict__ coefp) {
    int i = blockIdx.x * blockDim.x + threadIdx.x;
    int stride = gridDim.x * blockDim.x;
    float4 z = make_float4(0.f, 0.f, 0.f, 0.f);
    float4* a4 = reinterpret_cast<float4*>(g_aggf);
    for (int idx = i; idx < NN * CC / 4; idx += stride) a4[idx] = z;
    if (i >= EE) return;
    float coef = __ldg(coefp);
    int src = ei[i];
    float s = fmaf(coef, ew[i], 1.0f);
    atomicAdd(&g_cs[src].x, s);
    atomicAdd(&g_cs[src].y, s * s);
}

// ---------------- K2: Y = X @ pool_W via HMMA (fp16 in, fp32 accum) -----------
__global__ void __launch_bounds__(256) k2_xw(const float* __restrict__ x,
                                             const float* __restrict__ W) {
    __shared__ __align__(16) __half xs[128 * 72];
    __shared__ __align__(16) __half ws[64 * 72];
    __shared__ float s1buf[8][64];
    __shared__ float s2buf[8][64];

    int tid = threadIdx.x;
    int rowbase = blockIdx.x * 128;

    for (int i = tid; i < CC * CC; i += 256) {
        int k = i >> 6, c = i & 63;
        ws[c * 72 + k] = __float2half_rn(W[i]);
    }
    const float4 z4 = make_float4(0.f, 0.f, 0.f, 0.f);
    for (int i = tid; i < 128 * 16; i += 256) {
        int r = i >> 4, c4 = i & 15;
        int row = rowbase + r;
        float4 v = (row < NN) ? *reinterpret_cast<const float4*>(x + (size_t)row * CC + c4 * 4)
                              : z4;
        __half2* d = reinterpret_cast<__half2*>(&xs[r * 72 + c4 * 4]);
        d[0] = __floats2half2_rn(v.x, v.y);
        d[1] = __floats2half2_rn(v.z, v.w);
    }
    __syncthreads();

    int wid  = tid >> 5;
    int lane = tid & 31;
    int g = lane >> 2;
    int q = lane & 3;
    int rloc = wid * 16;

    unsigned afr[4][4];
#pragma unroll
    for (int ks = 0; ks < 4; ks++) {
        int k0 = ks * 16 + 2 * q;
        afr[ks][0] = *reinterpret_cast<const unsigned*>(&xs[(rloc + g) * 72 + k0]);
        afr[ks][1] = *reinterpret_cast<const unsigned*>(&xs[(rloc + g + 8) * 72 + k0]);
        afr[ks][2] = *reinterpret_cast<const unsigned*>(&xs[(rloc + g) * 72 + k0 + 8]);
        afr[ks][3] = *reinterpret_cast<const unsigned*>(&xs[(rloc + g + 8) * 72 + k0 + 8]);
    }

    float c[8][4];
#pragma unroll
    for (int nt = 0; nt < 8; nt++)
#pragma unroll
        for (int v = 0; v < 4; v++) c[nt][v] = 0.f;

#pragma unroll
    for (int nt = 0; nt < 8; nt++) {
        int n = nt * 8 + g;
#pragma unroll
        for (int ks = 0; ks < 4; ks++) {
            int kk = ks * 16 + 2 * q;
            unsigned b0 = *reinterpret_cast<const unsigned*>(&ws[n * 72 + kk]);
            unsigned b1 = *reinterpret_cast<const unsigned*>(&ws[n * 72 + kk + 8]);
            MMA16816(c[nt][0], c[nt][1], c[nt][2], c[nt][3],
                     afr[ks][0], afr[ks][1], afr[ks][2], afr[ks][3], b0, b1);
        }
    }

    int row0 = rowbase + rloc + g;
    int row1 = row0 + 8;
    bool ok0 = row0 < NN, ok1 = row1 < NN;
    float2 cs0 = ok0 ? g_cs[row0] : make_float2(0.f, 0.f);
    float2 cs1 = ok1 ? g_cs[row1] : make_float2(0.f, 0.f);

#pragma unroll
    for (int nt = 0; nt < 8; nt++) {
        if (ok0) g_Yh[(size_t)row0 * 32 + nt * 4 + q] = __floats2half2_rn(c[nt][0], c[nt][1]);
        if (ok1) g_Yh[(size_t)row1 * 32 + nt * 4 + q] = __floats2half2_rn(c[nt][2], c[nt][3]);
        float s1a = cs0.x * c[nt][0] + cs1.x * c[nt][2];
        float s1b = cs0.x * c[nt][1] + cs1.x * c[nt][3];
        float s2a = cs0.y * c[nt][0] * c[nt][0] + cs1.y * c[nt][2] * c[nt][2];
        float s2b = cs0.y * c[nt][1] * c[nt][1] + cs1.y * c[nt][3] * c[nt][3];
#pragma unroll
        for (int off = 4; off < 32; off <<= 1) {
            s1a += __shfl_xor_sync(0xffffffffu, s1a, off);
            s1b += __shfl_xor_sync(0xffffffffu, s1b, off);
            s2a += __shfl_xor_sync(0xffffffffu, s2a, off);
            s2b += __shfl_xor_sync(0xffffffffu, s2b, off);
        }
        if (g == 0) {
            s1buf[wid][nt * 8 + 2 * q]     = s1a;
            s1buf[wid][nt * 8 + 2 * q + 1] = s1b;
            s2buf[wid][nt * 8 + 2 * q]     = s2a;
            s2buf[wid][nt * 8 + 2 * q + 1] = s2b;
        }
    }
    __syncthreads();
    if (tid < CC) {
        float a = 0.f, b = 0.f;
#pragma unroll
        for (int w = 0; w < 8; w++) { a += s1buf[w][tid]; b += s2buf[w][tid]; }
        atomicAdd(&g_S1[tid], a);
        atomicAdd(&g_S2[tid], b);
    }
}

// ---------------- K4: filtered scatter-max (round-6 exact shape) ---------------
__global__ void __launch_bounds__(256) k4_scatter(const int* __restrict__ ei,
                                                  const float* __restrict__ ew,
                                                  const float* __restrict__ coefp,
                                                  const float* __restrict__ pb,
                                                  const float* __restrict__ gamma,
                                                  const float* __restrict__ beta) {
    __shared__ float s_al[CC], s_de[CC];
    if (threadIdx.x < CC) {
        int c = threadIdx.x;
        float invE = 1.0f / (float)EE;
        float bb = pb[c];
        float mean = g_S1[c] * invE + bb;
        float msq = (g_S2[c] + 2.f * bb * g_S1[c]) * invE + bb * bb;
        float var = msq - mean * mean;
        float alpha = gamma[c] * rsqrtf(var + BN_EPS);
        s_al[c] = alpha;
        s_de[c] = beta[c] + alpha * (bb - mean);
    }
    __syncthreads();
    float coef = __ldg(coefp);
    int lane = threadIdx.x & 31;
    int warp = (blockIdx.x * blockDim.x + threadIdx.x) >> 5;
    int nwarps = (gridDim.x * blockDim.x) >> 5;
    float al0 = s_al[2 * lane], al1 = s_al[2 * lane + 1];
    float de0 = s_de[2 * lane], de1 = s_de[2 * lane + 1];
    for (int base = warp * 32; base < EE; base += nwarps * 32) {
        int e = base + lane;
        int src = ei[e];
        int dst = ei[EE + e];
        float s = fmaf(coef, ew[e], 1.0f);
#pragma unroll 8
        for (int i = 0; i < 32; i++) {
            int   sI = __shfl_sync(0xffffffffu, src, i);
            int   dI = __shfl_sync(0xffffffffu, dst, i);
            float sS = __shfl_sync(0xffffffffu, s, i);
            __half2 yh = __ldg(g_Yh + (size_t)sI * 32 + lane);
            float2 yv = __half22float2(yh);
            float v0 = fmaf(al0 * sS, yv.x, de0);
            float v1 = fmaf(al1 * sS, yv.y, de1);
            float* arow = g_aggf + (size_t)dI * CC + 2 * lane;
            float2 cur = *reinterpret_cast<const float2*>(arow);
            unsigned* au = reinterpret_cast<unsigned*>(arow);
            if (v0 > cur.x) atomicMax(au,     __float_as_uint(v0));
            if (v1 > cur.y) atomicMax(au + 1, __float_as_uint(v1));
        }
    }
}

// ---------------- K5: h = [x‖agg] @ final_W + fb via HMMA, 2 K-phases ----------
// 256 threads (8 warps), block tile 128 rows x 64 cols. Phase 0: x (k 0..63),
// phase 1: agg (k 64..127); same smem tiles restaged. fp32 h to out + stats.
__global__ void __launch_bounds__(256) k5_final(const float* __restrict__ x,
                                                const float* __restrict__ Wf,
                                                const float* __restrict__ fb,
                                                float* __restrict__ hout) {
    __shared__ __align__(16) __half xs[128 * 72];
    __shared__ __align__(16) __half ws[64 * 72];
    __shared__ float s1buf[8][64];
    __shared__ float s2buf[8][64];

    int tid = threadIdx.x;
    int rowbase = blockIdx.x * 128;
    int wid  = tid >> 5;
    int lane = tid & 31;
    int g = lane >> 2;
    int q = lane & 3;
    int rloc = wid * 16;

    float c[8][4];
#pragma unroll
    for (int nt = 0; nt < 8; nt++) {
        int col = nt * 8 + 2 * q;
        float b0 = __ldg(fb + col), b1 = __ldg(fb + col + 1);
        c[nt][0] = b0; c[nt][1] = b1; c[nt][2] = b0; c[nt][3] = b1;
    }

    const float4 z4 = make_float4(0.f, 0.f, 0.f, 0.f);
#pragma unroll
    for (int ph = 0; ph < 2; ph++) {
        const float* src = (ph == 0) ? x : g_aggf;
        // stage W half (rows ph*64 + k), transposed fp16
        for (int i = tid; i < CC * CC; i += 256) {
            int k = i >> 6, cc = i & 63;
            ws[cc * 72 + k] = __float2half_rn(Wf[(size_t)(ph * 64 + k) * CC + cc]);
        }
        // stage src tile fp16
        for (int i = tid; i < 128 * 16; i += 256) {
            int r = i >> 4, c4 = i & 15;
            int row = rowbase + r;
            float4 v = (row < NN) ? *reinterpret_cast<const float4*>(src + (size_t)row * CC + c4 * 4)
                                  : z4;
            __half2* d = reinterpret_cast<__half2*>(&xs[r * 72 + c4 * 4]);
            d[0] = __floats2half2_rn(v.x, v.y);
            d[1] = __floats2half2_rn(v.z, v.w);
        }
        __syncthreads();

        unsigned afr[4][4];
#pragma unroll
        for (int ks = 0; ks < 4; ks++) {
            int k0 = ks * 16 + 2 * q;
            afr[ks][0] = *reinterpret_cast<const unsigned*>(&xs[(rloc + g) * 72 + k0]);
            afr[ks][1] = *reinterpret_cast<const unsigned*>(&xs[(rloc + g + 8) * 72 + k0]);
            afr[ks][2] = *reinterpret_cast<const unsigned*>(&xs[(rloc + g) * 72 + k0 + 8]);
            afr[ks][3] = *reinterpret_cast<const unsigned*>(&xs[(rloc + g + 8) * 72 + k0 + 8]);
        }
#pragma unroll
        for (int nt = 0; nt < 8; nt++) {
            int n = nt * 8 + g;
#pragma unroll
            for (int ks = 0; ks < 4; ks++) {
                int kk = ks * 16 + 2 * q;
                unsigned b0 = *reinterpret_cast<const unsigned*>(&ws[n * 72 + kk]);
                unsigned b1 = *reinterpret_cast<const unsigned*>(&ws[n * 72 + kk + 8]);
                MMA16816(c[nt][0], c[nt][1], c[nt][2], c[nt][3],
                         afr[ks][0], afr[ks][1], afr[ks][2], afr[ks][3], b0, b1);
            }
        }
        __syncthreads();   // tiles restaged next phase
    }

    // epilogue: store h (fp32) + per-channel stats
    int row0 = rowbase + rloc + g;
    int row1 = row0 + 8;
    bool ok0 = row0 < NN, ok1 = row1 < NN;
    float m0 = ok0 ? 1.f : 0.f, m1 = ok1 ? 1.f : 0.f;

#pragma unroll
    for (int nt = 0; nt < 8; nt++) {
        int col = nt * 8 + 2 * q;
        if (ok0) *reinterpret_cast<float2*>(hout + (size_t)row0 * CC + col) =
            make_float2(c[nt][0], c[nt][1]);
        if (ok1) *reinterpret_cast<float2*>(hout + (size_t)row1 * CC + col) =
            make_float2(c[nt][2], c[nt][3]);
        float s1a = m0 * c[nt][0] + m1 * c[nt][2];
        float s1b = m0 * c[nt][1] + m1 * c[nt][3];
        float s2a = m0 * c[nt][0] * c[nt][0] + m1 * c[nt][2] * c[nt][2];
        float s2b = m0 * c[nt][1] * c[nt][1] + m1 * c[nt][3] * c[nt][3];
#pragma unroll
        for (int off = 4; off < 32; off <<= 1) {
            s1a += __shfl_xor_sync(0xffffffffu, s1a, off);
            s1b += __shfl_xor_sync(0xffffffffu, s1b, off);
            s2a += __shfl_xor_sync(0xffffffffu, s2a, off);
            s2b += __shfl_xor_sync(0xffffffffu, s2b, off);
        }
        if (g == 0) {
            s1buf[wid][col]     = s1a;
            s1buf[wid][col + 1] = s1b;
            s2buf[wid][col]     = s2a;
            s2buf[wid][col + 1] = s2b;
        }
    }
    __syncthreads();
    if (tid < CC) {
        float a = 0.f, b = 0.f;
#pragma unroll
        for (int w = 0; w < 8; w++) { a += s1buf[w][tid]; b += s2buf[w][tid]; }
        atomicAdd(&g_hsum[tid], a);
        atomicAdd(&g_hsq[tid], b);
    }
}

// ---------------- K7: out = relu(a2*out + b2), in place (BN coeffs fused) ------
__global__ void __launch_bounds__(256) k7_epilogue(float* __restrict__ out,
                                                   const float* __restrict__ gamma,
                                                   const float* __restrict__ beta) {
    __shared__ float s_a[CC], s_b[CC];
    if (threadIdx.x < CC) {
        int c = threadIdx.x;
        float invN = 1.0f / (float)NN;
        float mean = g_hsum[c] * invN;
        float var = g_hsq[c] * invN - mean * mean;
        float a = gamma[c] * rsqrtf(var + BN_EPS);
        s_a[c] = a;
        s_b[c] = beta[c] - a * mean;
    }
    __syncthreads();
    int i = blockIdx.x * blockDim.x + threadIdx.x;
    int stride = gridDim.x * blockDim.x;
    float4* ov = reinterpret_cast<float4*>(out);
    for (int q = i; q < NN * 16; q += stride) {
        int c4 = (q & 15) * 4;
        float4 h = ov[q];
        float4 r;
        r.x = fmaxf(0.f, fmaf(s_a[c4 + 0], h.x, s_b[c4 + 0]));
        r.y = fmaxf(0.f, fmaf(s_a[c4 + 1], h.y, s_b[c4 + 1]));
        r.z = fmaxf(0.f, fmaf(s_a[c4 + 2], h.z, s_b[c4 + 2]));
        r.w = fmaxf(0.f, fmaf(s_a[c4 + 3], h.w, s_b[c4 + 3]));
        ov[q] = r;
    }
}

// ---------------- launch ---------------------------------------------------------
extern "C" void kernel_launch(void* const* d_in, const int* in_sizes, int n_in,
                              void* d_out, int out_size) {
    const float* x     = (const float*)d_in[0];
    const int*   ei    = (const int*)d_in[1];
    const float* ew    = (const float*)d_in[2];
    const float* pW    = (const float*)d_in[3];
    const float* pb    = (const float*)d_in[4];
    const float* pg    = (const float*)d_in[5];
    const float* pbeta = (const float*)d_in[6];
    const float* fW    = (const float*)d_in[7];
    const float* fb    = (const float*)d_in[8];
    const float* fg    = (const float*)d_in[9];
    const float* fbeta = (const float*)d_in[10];
    const float* coef  = (const float*)d_in[11];
    float* out = (float*)d_out;

    const int rowBlocks = (NN + 127) / 128;   // 391
    k0_zero<<<(NN + 255) / 256, 256>>>();
    k1_edge_stats<<<(EE + 255) / 256, 256>>>(ei, ew, coef);
    k2_xw<<<rowBlocks, 256>>>(x, pW);
    k4_scatter<<<1184, 256>>>(ei, ew, coef, pb, pg, pbeta);
    k5_final<<<rowBlocks, 256>>>(x, fW, fb, out);
    k7_epilogue<<<1024, 256>>>(out, fg, fbeta);
}

// round 17
// speedup vs baseline: 1.5883x; 1.1274x over previous
#include <cuda_runtime.h>
#include <cuda_fp16.h>

#define NN 50000
#define EE 800000
#define CC 64
#define BN_EPS 1e-5f

#define MMA16816(c0, c1, c2, c3, a0, a1, a2, a3, b0, b1) \
    asm volatile("mma.sync.aligned.m16n8k16.row.col.f32.f16.f16.f32 " \
        "{%0,%1,%2,%3}, {%4,%5,%6,%7}, {%8,%9}, {%0,%1,%2,%3};" \
        : "+f"(c0), "+f"(c1), "+f"(c2), "+f"(c3) \
        : "r"(a0), "r"(a1), "r"(a2), "r"(a3), "r"(b0), "r"(b1))

// packed fp16 componentwise max reduction (sm_90+), vector form, no return
#define REDMAX_V2F16(ptr, lo, hi) \
    asm volatile("red.global.max.noftz.v2.f16 [%0], {%1, %2};" \
        :: "l"(ptr), "h"(lo), "h"(hi) : "memory")

// ---------------- scratch (static device arrays; no allocation) -------------
__device__ float2   g_cs[NN];        // (sum s, sum s^2) per src node
__device__ float    g_S1[CC];
__device__ float    g_S2[CC];
__device__ float    g_hsum[CC];
__device__ float    g_hsq[CC];
__device__ __half2  g_Yh[NN * 32];   // X @ pool_W, fp16x2 (k4 gather only)
__device__ __half2  g_aggh[NN * 32]; // scatter-max result, fp16x2 (>= 0)

// ---------------- K0: zero small per-replay state -----------------------------
__global__ void k0_zero() {
    int i = blockIdx.x * blockDim.x + threadIdx.x;
    if (i < NN) g_cs[i] = make_float2(0.f, 0.f);
    if (i < CC) { g_S1[i] = 0.f; g_S2[i] = 0.f; g_hsum[i] = 0.f; g_hsq[i] = 0.f; }
}

// ---------------- K1: per-src sums of s, s^2 + zero agg ------------------------
__global__ void k1_edge_stats(const int* __restrict__ ei,
                              const float* __restrict__ ew,
                              const float* __restrict__ coefp) {
    int i = blockIdx.x * blockDim.x + threadIdx.x;
    int stride = gridDim.x * blockDim.x;
    // zero scatter-max target: NN*32 half2 = NN*128 bytes = NN*8 float4s
    float4 z = make_float4(0.f, 0.f, 0.f, 0.f);
    float4* a4 = reinterpret_cast<float4*>(g_aggh);
    for (int idx = i; idx < NN * 8; idx += stride) a4[idx] = z;
    if (i >= EE) return;
    float coef = __ldg(coefp);
    int src = ei[i];
    float s = fmaf(coef, ew[i], 1.0f);
    atomicAdd(&g_cs[src].x, s);
    atomicAdd(&g_cs[src].y, s * s);
}

// ---------------- K2: Y = X @ pool_W via HMMA (fp16 in, fp32 accum) -----------
__global__ void __launch_bounds__(256) k2_xw(const float* __restrict__ x,
                                             const float* __restrict__ W) {
    __shared__ __align__(16) __half xs[128 * 72];
    __shared__ __align__(16) __half ws[64 * 72];
    __shared__ float s1buf[8][64];
    __shared__ float s2buf[8][64];

    int tid = threadIdx.x;
    int rowbase = blockIdx.x * 128;

    for (int i = tid; i < CC * CC; i += 256) {
        int k = i >> 6, c = i & 63;
        ws[c * 72 + k] = __float2half_rn(W[i]);
    }
    const float4 z4 = make_float4(0.f, 0.f, 0.f, 0.f);
    for (int i = tid; i < 128 * 16; i += 256) {
        int r = i >> 4, c4 = i & 15;
        int row = rowbase + r;
        float4 v = (row < NN) ? *reinterpret_cast<const float4*>(x + (size_t)row * CC + c4 * 4)
                              : z4;
        __half2* d = reinterpret_cast<__half2*>(&xs[r * 72 + c4 * 4]);
        d[0] = __floats2half2_rn(v.x, v.y);
        d[1] = __floats2half2_rn(v.z, v.w);
    }
    __syncthreads();

    int wid  = tid >> 5;
    int lane = tid & 31;
    int g = lane >> 2;
    int q = lane & 3;
    int rloc = wid * 16;

    unsigned afr[4][4];
#pragma unroll
    for (int ks = 0; ks < 4; ks++) {
        int k0 = ks * 16 + 2 * q;
        afr[ks][0] = *reinterpret_cast<const unsigned*>(&xs[(rloc + g) * 72 + k0]);
        afr[ks][1] = *reinterpret_cast<const unsigned*>(&xs[(rloc + g + 8) * 72 + k0]);
        afr[ks][2] = *reinterpret_cast<const unsigned*>(&xs[(rloc + g) * 72 + k0 + 8]);
        afr[ks][3] = *reinterpret_cast<const unsigned*>(&xs[(rloc + g + 8) * 72 + k0 + 8]);
    }

    float c[8][4];
#pragma unroll
    for (int nt = 0; nt < 8; nt++)
#pragma unroll
        for (int v = 0; v < 4; v++) c[nt][v] = 0.f;

#pragma unroll
    for (int nt = 0; nt < 8; nt++) {
        int n = nt * 8 + g;
#pragma unroll
        for (int ks = 0; ks < 4; ks++) {
            int kk = ks * 16 + 2 * q;
            unsigned b0 = *reinterpret_cast<const unsigned*>(&ws[n * 72 + kk]);
            unsigned b1 = *reinterpret_cast<const unsigned*>(&ws[n * 72 + kk + 8]);
            MMA16816(c[nt][0], c[nt][1], c[nt][2], c[nt][3],
                     afr[ks][0], afr[ks][1], afr[ks][2], afr[ks][3], b0, b1);
        }
    }

    int row0 = rowbase + rloc + g;
    int row1 = row0 + 8;
    bool ok0 = row0 < NN, ok1 = row1 < NN;
    float2 cs0 = ok0 ? g_cs[row0] : make_float2(0.f, 0.f);
    float2 cs1 = ok1 ? g_cs[row1] : make_float2(0.f, 0.f);

#pragma unroll
    for (int nt = 0; nt < 8; nt++) {
        if (ok0) g_Yh[(size_t)row0 * 32 + nt * 4 + q] = __floats2half2_rn(c[nt][0], c[nt][1]);
        if (ok1) g_Yh[(size_t)row1 * 32 + nt * 4 + q] = __floats2half2_rn(c[nt][2], c[nt][3]);
        float s1a = cs0.x * c[nt][0] + cs1.x * c[nt][2];
        float s1b = cs0.x * c[nt][1] + cs1.x * c[nt][3];
        float s2a = cs0.y * c[nt][0] * c[nt][0] + cs1.y * c[nt][2] * c[nt][2];
        float s2b = cs0.y * c[nt][1] * c[nt][1] + cs1.y * c[nt][3] * c[nt][3];
#pragma unroll
        for (int off = 4; off < 32; off <<= 1) {
            s1a += __shfl_xor_sync(0xffffffffu, s1a, off);
            s1b += __shfl_xor_sync(0xffffffffu, s1b, off);
            s2a += __shfl_xor_sync(0xffffffffu, s2a, off);
            s2b += __shfl_xor_sync(0xffffffffu, s2b, off);
        }
        if (g == 0) {
            s1buf[wid][nt * 8 + 2 * q]     = s1a;
            s1buf[wid][nt * 8 + 2 * q + 1] = s1b;
            s2buf[wid][nt * 8 + 2 * q]     = s2a;
            s2buf[wid][nt * 8 + 2 * q + 1] = s2b;
        }
    }
    __syncthreads();
    if (tid < CC) {
        float a = 0.f, b = 0.f;
#pragma unroll
        for (int w = 0; w < 8; w++) { a += s1buf[w][tid]; b += s2buf[w][tid]; }
        atomicAdd(&g_S1[tid], a);
        atomicAdd(&g_S2[tid], b);
    }
}

// ---------------- K4: filtered scatter-max, fp16 agg + v2.f16 RED --------------
__global__ void __launch_bounds__(256) k4_scatter(const int* __restrict__ ei,
                                                  const float* __restrict__ ew,
                                                  const float* __restrict__ coefp,
                                                  const float* __restrict__ pb,
                                                  const float* __restrict__ gamma,
                                                  const float* __restrict__ beta) {
    __shared__ float s_al[CC], s_de[CC];
    if (threadIdx.x < CC) {
        int c = threadIdx.x;
        float invE = 1.0f / (float)EE;
        float bb = pb[c];
        float mean = g_S1[c] * invE + bb;
        float msq = (g_S2[c] + 2.f * bb * g_S1[c]) * invE + bb * bb;
        float var = msq - mean * mean;
        float alpha = gamma[c] * rsqrtf(var + BN_EPS);
        s_al[c] = alpha;
        s_de[c] = beta[c] + alpha * (bb - mean);
    }
    __syncthreads();
    float coef = __ldg(coefp);
    int lane = threadIdx.x & 31;
    int warp = (blockIdx.x * blockDim.x + threadIdx.x) >> 5;
    int nwarps = (gridDim.x * blockDim.x) >> 5;
    float al0 = s_al[2 * lane], al1 = s_al[2 * lane + 1];
    float de0 = s_de[2 * lane], de1 = s_de[2 * lane + 1];
    for (int base = warp * 32; base < EE; base += nwarps * 32) {
        int e = base + lane;
        int src = ei[e];
        int dst = ei[EE + e];
        float s = fmaf(coef, ew[e], 1.0f);
#pragma unroll 8
        for (int i = 0; i < 32; i++) {
            int   sI = __shfl_sync(0xffffffffu, src, i);
            int   dI = __shfl_sync(0xffffffffu, dst, i);
            float sS = __shfl_sync(0xffffffffu, s, i);
            __half2 yh = __ldg(g_Yh + (size_t)sI * 32 + lane);
            float2 yv = __half22float2(yh);
            float v0 = fmaf(al0 * sS, yv.x, de0);
            float v1 = fmaf(al1 * sS, yv.y, de1);
            __half2 hv = __floats2half2_rn(v0, v1);
            __half2* arow = g_aggh + (size_t)dI * 32 + lane;
            __half2 cur = *arow;
            if (__hgt(__low2half(hv), __low2half(cur)) ||
                __hgt(__high2half(hv), __high2half(cur))) {
                unsigned hvu = *reinterpret_cast<unsigned*>(&hv);
                unsigned short lo = (unsigned short)(hvu & 0xffffu);
                unsigned short hi = (unsigned short)(hvu >> 16);
                REDMAX_V2F16(arow, lo, hi);
            }
        }
    }
}

// ---------------- K5: h = [x‖agg] @ final_W + fb via HMMA, 2 K-phases ----------
__global__ void __launch_bounds__(256) k5_final(const float* __restrict__ x,
                                                const float* __restrict__ Wf,
                                                const float* __restrict__ fb,
                                                float* __restrict__ hout) {
    __shared__ __align__(16) __half xs[128 * 72];
    __shared__ __align__(16) __half ws[64 * 72];
    __shared__ float s1buf[8][64];
    __shared__ float s2buf[8][64];

    int tid = threadIdx.x;
    int rowbase = blockIdx.x * 128;
    int wid  = tid >> 5;
    int lane = tid & 31;
    int g = lane >> 2;
    int q = lane & 3;
    int rloc = wid * 16;

    float c[8][4];
#pragma unroll
    for (int nt = 0; nt < 8; nt++) {
        int col = nt * 8 + 2 * q;
        float b0 = __ldg(fb + col), b1 = __ldg(fb + col + 1);
        c[nt][0] = b0; c[nt][1] = b1; c[nt][2] = b0; c[nt][3] = b1;
    }

    const float4 z4 = make_float4(0.f, 0.f, 0.f, 0.f);
#pragma unroll
    for (int ph = 0; ph < 2; ph++) {
        // stage W half (rows ph*64 + k), transposed fp16
        for (int i = tid; i < CC * CC; i += 256) {
            int k = i >> 6, cc = i & 63;
            ws[cc * 72 + k] = __float2half_rn(Wf[(size_t)(ph * 64 + k) * CC + cc]);
        }
        if (ph == 0) {
            // stage x tile (fp32 -> fp16)
            for (int i = tid; i < 128 * 16; i += 256) {
                int r = i >> 4, c4 = i & 15;
                int row = rowbase + r;
                float4 v = (row < NN) ? *reinterpret_cast<const float4*>(x + (size_t)row * CC + c4 * 4)
                                      : z4;
                __half2* d = reinterpret_cast<__half2*>(&xs[r * 72 + c4 * 4]);
                d[0] = __floats2half2_rn(v.x, v.y);
                d[1] = __floats2half2_rn(v.z, v.w);
            }
        } else {
            // stage agg tile (already fp16): straight uint4 copy
            const uint4 zu = make_uint4(0u, 0u, 0u, 0u);
            for (int i = tid; i < 128 * 8; i += 256) {
                int r = i >> 3, c8 = i & 7;
                int row = rowbase + r;
                uint4 v = (row < NN)
                    ? *reinterpret_cast<const uint4*>(g_aggh + (size_t)row * 32 + c8 * 4)
                    : zu;
                *reinterpret_cast<uint4*>(&xs[r * 72 + c8 * 8]) = v;
            }
        }
        __syncthreads();

        unsigned afr[4][4];
#pragma unroll
        for (int ks = 0; ks < 4; ks++) {
            int k0 = ks * 16 + 2 * q;
            afr[ks][0] = *reinterpret_cast<const unsigned*>(&xs[(rloc + g) * 72 + k0]);
            afr[ks][1] = *reinterpret_cast<const unsigned*>(&xs[(rloc + g + 8) * 72 + k0]);
            afr[ks][2] = *reinterpret_cast<const unsigned*>(&xs[(rloc + g) * 72 + k0 + 8]);
            afr[ks][3] = *reinterpret_cast<const unsigned*>(&xs[(rloc + g + 8) * 72 + k0 + 8]);
        }
#pragma unroll
        for (int nt = 0; nt < 8; nt++) {
            int n = nt * 8 + g;
#pragma unroll
            for (int ks = 0; ks < 4; ks++) {
                int kk = ks * 16 + 2 * q;
                unsigned b0 = *reinterpret_cast<const unsigned*>(&ws[n * 72 + kk]);
                unsigned b1 = *reinterpret_cast<const unsigned*>(&ws[n * 72 + kk + 8]);
                MMA16816(c[nt][0], c[nt][1], c[nt][2], c[nt][3],
                         afr[ks][0], afr[ks][1], afr[ks][2], afr[ks][3], b0, b1);
            }
        }
        __syncthreads();   // tiles restaged next phase
    }

    // epilogue: store h (fp32) + per-channel stats
    int row0 = rowbase + rloc + g;
    int row1 = row0 + 8;
    bool ok0 = row0 < NN, ok1 = row1 < NN;
    float m0 = ok0 ? 1.f : 0.f, m1 = ok1 ? 1.f : 0.f;

#pragma unroll
    for (int nt = 0; nt < 8; nt++) {
        int col = nt * 8 + 2 * q;
        if (ok0) *reinterpret_cast<float2*>(hout + (size_t)row0 * CC + col) =
            make_float2(c[nt][0], c[nt][1]);
        if (ok1) *reinterpret_cast<float2*>(hout + (size_t)row1 * CC + col) =
            make_float2(c[nt][2], c[nt][3]);
        float s1a = m0 * c[nt][0] + m1 * c[nt][2];
        float s1b = m0 * c[nt][1] + m1 * c[nt][3];
        float s2a = m0 * c[nt][0] * c[nt][0] + m1 * c[nt][2] * c[nt][2];
        float s2b = m0 * c[nt][1] * c[nt][1] + m1 * c[nt][3] * c[nt][3];
#pragma unroll
        for (int off = 4; off < 32; off <<= 1) {
            s1a += __shfl_xor_sync(0xffffffffu, s1a, off);
            s1b += __shfl_xor_sync(0xffffffffu, s1b, off);
            s2a += __shfl_xor_sync(0xffffffffu, s2a, off);
            s2b += __shfl_xor_sync(0xffffffffu, s2b, off);
        }
        if (g == 0) {
            s1buf[wid][col]     = s1a;
            s1buf[wid][col + 1] = s1b;
            s2buf[wid][col]     = s2a;
            s2buf[wid][col + 1] = s2b;
        }
    }
    __syncthreads();
    if (tid < CC) {
        float a = 0.f, b = 0.f;
#pragma unroll
        for (int w = 0; w < 8; w++) { a += s1buf[w][tid]; b += s2buf[w][tid]; }
        atomicAdd(&g_hsum[tid], a);
        atomicAdd(&g_hsq[tid], b);
    }
}

// ---------------- K7: out = relu(a2*out + b2), in place (BN coeffs fused) ------
__global__ void __launch_bounds__(256) k7_epilogue(float* __restrict__ out,
                                                   const float* __restrict__ gamma,
                                                   const float* __restrict__ beta) {
    __shared__ float s_a[CC], s_b[CC];
    if (threadIdx.x < CC) {
        int c = threadIdx.x;
        float invN = 1.0f / (float)NN;
        float mean = g_hsum[c] * invN;
        float var = g_hsq[c] * invN - mean * mean;
        float a = gamma[c] * rsqrtf(var + BN_EPS);
        s_a[c] = a;
        s_b[c] = beta[c] - a * mean;
    }
    __syncthreads();
    int i = blockIdx.x * blockDim.x + threadIdx.x;
    int stride = gridDim.x * blockDim.x;
    float4* ov = reinterpret_cast<float4*>(out);
    for (int q = i; q < NN * 16; q += stride) {
        int c4 = (q & 15) * 4;
        float4 h = ov[q];
        float4 r;
        r.x = fmaxf(0.f, fmaf(s_a[c4 + 0], h.x, s_b[c4 + 0]));
        r.y = fmaxf(0.f, fmaf(s_a[c4 + 1], h.y, s_b[c4 + 1]));
        r.z = fmaxf(0.f, fmaf(s_a[c4 + 2], h.z, s_b[c4 + 2]));
        r.w = fmaxf(0.f, fmaf(s_a[c4 + 3], h.w, s_b[c4 + 3]));
        ov[q] = r;
    }
}

// ---------------- launch ---------------------------------------------------------
extern "C" void kernel_launch(void* const* d_in, const int* in_sizes, int n_in,
                              void* d_out, int out_size) {
    const float* x     = (const float*)d_in[0];
    const int*   ei    = (const int*)d_in[1];
    const float* ew    = (const float*)d_in[2];
    const float* pW    = (const float*)d_in[3];
    const float* pb    = (const float*)d_in[4];
    const float* pg    = (const float*)d_in[5];
    const float* pbeta = (const float*)d_in[6];
    const float* fW    = (const float*)d_in[7];
    const float* fb    = (const float*)d_in[8];
    const float* fg    = (const float*)d_in[9];
    const float* fbeta = (const float*)d_in[10];
    const float* coef  = (const float*)d_in[11];
    float* out = (float*)d_out;

    const int rowBlocks = (NN + 127) / 128;   // 391
    k0_zero<<<(NN + 255) / 256, 256>>>();
    k1_edge_stats<<<(EE + 255) / 256, 256>>>(ei, ew, coef);
    k2_xw<<<rowBlocks, 256>>>(x, pW);
    k4_scatter<<<1184, 256>>>(ei, ew, coef, pb, pg, pbeta);
    k5_final<<<rowBlocks, 256>>>(x, fW, fb, out);
    k7_epilogue<<<1024, 256>>>(out, fg, fbeta);
}